// round 3
// baseline (speedup 1.0000x reference)
#include <cuda_runtime.h>

#define N_NODES   100000
#define N_EDGES   1600000
#define N_GRAPHS  128
#define D         64
#define SCAN_NB   98          // ceil(100000/1024)

// ---------------- scratch (static __device__, no allocation) ----------------
__device__ int   g_deg [N_NODES];
__device__ int   g_off [N_NODES + 1];
__device__ int   g_fill[N_NODES];
__device__ int   g_csrc[N_EDGES];
__device__ int   g_bsum [128];
__device__ int   g_bpref[128];
__device__ float g_agg[(size_t)N_NODES * D];
__device__ float g_f  [(size_t)N_NODES * D];
__device__ float g_fg [N_GRAPHS * D];
__device__ float g_hg [N_GRAPHS * D];

// ---------------- zero per-launch state ----------------
__global__ void k_zero() {
    int i = blockIdx.x * blockDim.x + threadIdx.x;
    if (i < N_NODES) g_deg[i] = 0;
    if (i < N_GRAPHS * D) { g_fg[i] = 0.f; g_hg[i] = 0.f; }
}

// ---------------- CSR build ----------------
__global__ void k_hist(const int* __restrict__ dst) {
    int e = blockIdx.x * blockDim.x + threadIdx.x;
    if (e < N_EDGES) atomicAdd(&g_deg[dst[e]], 1);
}

__global__ void k_breduce() {
    __shared__ int sh[1024];
    int tid = threadIdx.x;
    int i = blockIdx.x * 1024 + tid;
    sh[tid] = (i < N_NODES) ? g_deg[i] : 0;
    __syncthreads();
    for (int s = 512; s > 0; s >>= 1) {
        if (tid < s) sh[tid] += sh[tid + s];
        __syncthreads();
    }
    if (tid == 0) g_bsum[blockIdx.x] = sh[0];
}

__global__ void k_bscan() {      // 1 block, 128 threads
    __shared__ int sh[128];
    int tid = threadIdx.x;
    int v = (tid < SCAN_NB) ? g_bsum[tid] : 0;
    sh[tid] = v;
    __syncthreads();
    for (int off = 1; off < 128; off <<= 1) {
        int t = (tid >= off) ? sh[tid - off] : 0;
        __syncthreads();
        sh[tid] += t;
        __syncthreads();
    }
    if (tid < SCAN_NB) g_bpref[tid] = sh[tid] - v;   // exclusive
}

__global__ void k_scan() {       // SCAN_NB blocks, 1024 threads
    __shared__ int sh[1024];
    int tid = threadIdx.x;
    int i = blockIdx.x * 1024 + tid;
    int v = (i < N_NODES) ? g_deg[i] : 0;
    sh[tid] = v;
    __syncthreads();
    for (int off = 1; off < 1024; off <<= 1) {
        int t = (tid >= off) ? sh[tid - off] : 0;
        __syncthreads();
        sh[tid] += t;
        __syncthreads();
    }
    int excl = g_bpref[blockIdx.x] + sh[tid] - v;
    if (i < N_NODES) {
        g_off[i]  = excl;
        g_fill[i] = excl;
        if (i == N_NODES - 1) g_off[N_NODES] = excl + v;
    }
}

__global__ void k_fill(const int* __restrict__ src, const int* __restrict__ dst) {
    int e = blockIdx.x * blockDim.x + threadIdx.x;
    if (e < N_EDGES) {
        int slot = atomicAdd(&g_fill[dst[e]], 1);
        g_csrc[slot] = src[e];
    }
}

// ---------------- mean aggregation: warp per node ----------------
// pass 0: x = feat (param),  pass 1: x = g_f.  out = g_agg always.
__global__ void k_agg(const float* __restrict__ feat, int pass) {
    const float* __restrict__ x = pass ? g_f : feat;
    int t    = blockIdx.x * 256 + threadIdx.x;
    int w    = t >> 5;
    int lane = t & 31;
    int s0 = g_off[w], s1 = g_off[w + 1];
    float a0 = 0.f, a1 = 0.f;
    for (int e = s0; e < s1; e++) {
        int s = g_csrc[e];
        const float* xr = x + (size_t)s * D;
        a0 += __ldg(xr + lane);
        a1 += __ldg(xr + lane + 32);
    }
    float* o = g_agg + (size_t)w * D;
    if (s1 > s0) {
        float inv = 1.f / (float)(s1 - s0);
        o[lane]      = a0 * inv;
        o[lane + 32] = a1 * inv;
    } else {
        const float* xr = x + (size_t)w * D;
        o[lane]      = xr[lane];
        o[lane + 32] = xr[lane + 32];
    }
}

// ---------------- fused node MLP: relu(x@Wa+ba) -> softmax(@Wb+bb) ----------------
// pass 0: in=g_agg, writes g_f, pools into g_fg
// pass 1: in=g_agg, no node output, pools into g_hg
__global__ void __launch_bounds__(256) k_mlp(
    const float* __restrict__ Wa, const float* __restrict__ ba,
    const float* __restrict__ Wb, const float* __restrict__ bb,
    const int* __restrict__ gid, int pass)
{
    __shared__ float2 sWa[64 * 32];
    __shared__ float2 sWb[64 * 32];
    __shared__ float  sba[64], sbb[64];
    __shared__ float  spool[64];
    __shared__ int    sgid[8];

    int tid = threadIdx.x;
    for (int idx = tid; idx < 64 * 32; idx += 256) {
        int k = idx >> 5, j = idx & 31;
        sWa[idx] = make_float2(Wa[k * 64 + j], Wa[k * 64 + j + 32]);
        sWb[idx] = make_float2(Wb[k * 64 + j], Wb[k * 64 + j + 32]);
    }
    if (tid < 64) { sba[tid] = ba[tid]; sbb[tid] = bb[tid]; spool[tid] = 0.f; }

    int warp = tid >> 5, lane = tid & 31;
    int row  = blockIdx.x * 8 + warp;
    if (lane == 0) sgid[warp] = gid[row];
    __syncthreads();

    const float* xr = g_agg + (size_t)row * D;
    float x0 = xr[lane], x1 = xr[lane + 32];

    float a0 = sba[lane], a1 = sba[lane + 32];
    #pragma unroll
    for (int k = 0; k < 32; k++) {
        float xk = __shfl_sync(0xffffffffu, x0, k);
        float2 w = sWa[k * 32 + lane];
        a0 = fmaf(xk, w.x, a0); a1 = fmaf(xk, w.y, a1);
    }
    #pragma unroll
    for (int k = 0; k < 32; k++) {
        float xk = __shfl_sync(0xffffffffu, x1, k);
        float2 w = sWa[(k + 32) * 32 + lane];
        a0 = fmaf(xk, w.x, a0); a1 = fmaf(xk, w.y, a1);
    }
    float h0 = fmaxf(a0, 0.f), h1 = fmaxf(a1, 0.f);

    float z0 = sbb[lane], z1 = sbb[lane + 32];
    #pragma unroll
    for (int k = 0; k < 32; k++) {
        float hk = __shfl_sync(0xffffffffu, h0, k);
        float2 w = sWb[k * 32 + lane];
        z0 = fmaf(hk, w.x, z0); z1 = fmaf(hk, w.y, z1);
    }
    #pragma unroll
    for (int k = 0; k < 32; k++) {
        float hk = __shfl_sync(0xffffffffu, h1, k);
        float2 w = sWb[(k + 32) * 32 + lane];
        z0 = fmaf(hk, w.x, z0); z1 = fmaf(hk, w.y, z1);
    }

    // softmax over the 64 features (2 per lane, warp-wide)
    float m = fmaxf(z0, z1);
    #pragma unroll
    for (int o = 16; o > 0; o >>= 1) m = fmaxf(m, __shfl_xor_sync(0xffffffffu, m, o));
    float e0 = __expf(z0 - m), e1 = __expf(z1 - m);
    float s = e0 + e1;
    #pragma unroll
    for (int o = 16; o > 0; o >>= 1) s += __shfl_xor_sync(0xffffffffu, s, o);
    float rinv = 1.f / s;
    float r0 = e0 * rinv, r1 = e1 * rinv;

    float* pool = pass ? g_hg : g_fg;
    if (pass == 0) {
        float* o_ = g_f + (size_t)row * D;
        o_[lane] = r0; o_[lane + 32] = r1;
    }

    // graph pooling: graph_ids sorted -> most blocks are single-graph.
    bool same = (sgid[0] == sgid[1]) && (sgid[1] == sgid[2]) && (sgid[2] == sgid[3]) &&
                (sgid[3] == sgid[4]) && (sgid[4] == sgid[5]) && (sgid[5] == sgid[6]) &&
                (sgid[6] == sgid[7]);
    if (same) {
        atomicAdd(&spool[lane],      r0);
        atomicAdd(&spool[lane + 32], r1);
        __syncthreads();
        if (tid < 64) atomicAdd(&pool[sgid[0] * D + tid], spool[tid]);
    } else {
        int g = sgid[warp];
        atomicAdd(&pool[g * D + lane],      r0);
        atomicAdd(&pool[g * D + lane + 32], r1);
    }
}

// ---------------- classifier head: warp per graph ----------------
__global__ void __launch_bounds__(1024) k_final(
    const float* __restrict__ Wd, const float* __restrict__ bd,
    const float* __restrict__ Wc, const float* __restrict__ bc,
    float* __restrict__ out)
{
    __shared__ float2 sWd[128 * 32];
    __shared__ float  sbd[64], sWc[64];
    int tid = threadIdx.x;
    for (int idx = tid; idx < 128 * 32; idx += 1024) {
        int k = idx >> 5, j = idx & 31;
        sWd[idx] = make_float2(Wd[k * 64 + j], Wd[k * 64 + j + 32]);
    }
    if (tid < 64) { sbd[tid] = bd[tid]; sWc[tid] = Wc[tid]; }
    __syncthreads();

    int warp = tid >> 5, lane = tid & 31;
    int g = blockIdx.x * 32 + warp;
    if (g >= N_GRAPHS) return;

    float xc0 = g_fg[g * D + lane];
    float xc1 = g_fg[g * D + lane + 32];
    float xc2 = xc0 + g_hg[g * D + lane];
    float xc3 = xc1 + g_hg[g * D + lane + 32];

    float a0 = sbd[lane], a1 = sbd[lane + 32];
    #pragma unroll
    for (int k = 0; k < 32; k++) {
        float xk = __shfl_sync(0xffffffffu, xc0, k);
        float2 w = sWd[k * 32 + lane];
        a0 = fmaf(xk, w.x, a0); a1 = fmaf(xk, w.y, a1);
    }
    #pragma unroll
    for (int k = 0; k < 32; k++) {
        float xk = __shfl_sync(0xffffffffu, xc1, k);
        float2 w = sWd[(k + 32) * 32 + lane];
        a0 = fmaf(xk, w.x, a0); a1 = fmaf(xk, w.y, a1);
    }
    #pragma unroll
    for (int k = 0; k < 32; k++) {
        float xk = __shfl_sync(0xffffffffu, xc2, k);
        float2 w = sWd[(k + 64) * 32 + lane];
        a0 = fmaf(xk, w.x, a0); a1 = fmaf(xk, w.y, a1);
    }
    #pragma unroll
    for (int k = 0; k < 32; k++) {
        float xk = __shfl_sync(0xffffffffu, xc3, k);
        float2 w = sWd[(k + 96) * 32 + lane];
        a0 = fmaf(xk, w.x, a0); a1 = fmaf(xk, w.y, a1);
    }
    float r0 = fmaxf(a0, 0.f), r1 = fmaxf(a1, 0.f);
    float p = r0 * sWc[lane] + r1 * sWc[lane + 32];
    #pragma unroll
    for (int o = 16; o > 0; o >>= 1) p += __shfl_xor_sync(0xffffffffu, p, o);
    if (lane == 0) out[g] = p + bc[0];
}

// ---------------- launch ----------------
extern "C" void kernel_launch(void* const* d_in, const int* in_sizes, int n_in,
                              void* d_out, int out_size)
{
    const float* feat = (const float*)d_in[0];
    const int*   src  = (const int*)  d_in[1];
    const int*   dst  = (const int*)  d_in[2];
    const int*   gid  = (const int*)  d_in[3];
    const float* W1   = (const float*)d_in[4];
    const float* b1   = (const float*)d_in[5];
    const float* Ws1  = (const float*)d_in[6];
    const float* bs1  = (const float*)d_in[7];
    const float* W2   = (const float*)d_in[8];
    const float* b2   = (const float*)d_in[9];
    const float* Ws2  = (const float*)d_in[10];
    const float* bs2  = (const float*)d_in[11];
    const float* Wd   = (const float*)d_in[12];
    const float* bd   = (const float*)d_in[13];
    const float* Wc   = (const float*)d_in[14];
    const float* bc   = (const float*)d_in[15];
    float* out = (float*)d_out;

    k_zero   <<<(N_NODES + 255) / 256, 256>>>();
    k_hist   <<<N_EDGES / 256, 256>>>(dst);
    k_breduce<<<SCAN_NB, 1024>>>();
    k_bscan  <<<1, 128>>>();
    k_scan   <<<SCAN_NB, 1024>>>();
    k_fill   <<<N_EDGES / 256, 256>>>(src, dst);

    k_agg  <<<N_NODES * 32 / 256, 256>>>(feat, 0);           // agg1(feat)
    k_mlp  <<<N_NODES / 8, 256>>>(W1, b1, Ws1, bs1, gid, 0); // -> g_f, pool g_fg
    k_agg  <<<N_NODES * 32 / 256, 256>>>(feat, 1);           // agg2(g_f)
    k_mlp  <<<N_NODES / 8, 256>>>(W2, b2, Ws2, bs2, gid, 1); // pool g_hg
    k_final<<<4, 1024>>>(Wd, bd, Wc, bc, out);
}

// round 4
// speedup vs baseline: 1.1512x; 1.1512x over previous
#include <cuda_runtime.h>

#define N_NODES   100000
#define N_EDGES   1600000
#define N_GRAPHS  128
#define D         64
#define SCAN_NB   98          // ceil(100000/1024)
#define GCN_GRID  1184        // 148 SMs * 8 blocks

// ---------------- scratch (static __device__, no allocation) ----------------
__device__ int   g_deg [N_NODES];
__device__ int   g_off [N_NODES + 1];
__device__ int   g_fill[N_NODES];
__device__ int   g_csrc[N_EDGES];
__device__ int   g_bsum [128];
__device__ int   g_bpref[128];
__device__ float g_f  [(size_t)N_NODES * D];
__device__ float g_fg [N_GRAPHS * D];
__device__ float g_hg [N_GRAPHS * D];

// ---------------- zero per-launch state ----------------
__global__ void k_zero() {
    int i = blockIdx.x * blockDim.x + threadIdx.x;
    if (i < N_NODES) g_deg[i] = 0;
    if (i < N_GRAPHS * D) { g_fg[i] = 0.f; g_hg[i] = 0.f; }
}

// ---------------- CSR build ----------------
__global__ void k_hist(const int* __restrict__ dst) {
    int e = blockIdx.x * blockDim.x + threadIdx.x;
    if (e < N_EDGES) atomicAdd(&g_deg[dst[e]], 1);
}

__global__ void k_breduce() {
    __shared__ int sh[1024];
    int tid = threadIdx.x;
    int i = blockIdx.x * 1024 + tid;
    sh[tid] = (i < N_NODES) ? g_deg[i] : 0;
    __syncthreads();
    for (int s = 512; s > 0; s >>= 1) {
        if (tid < s) sh[tid] += sh[tid + s];
        __syncthreads();
    }
    if (tid == 0) g_bsum[blockIdx.x] = sh[0];
}

__global__ void k_bscan() {      // 1 block, 128 threads
    __shared__ int sh[128];
    int tid = threadIdx.x;
    int v = (tid < SCAN_NB) ? g_bsum[tid] : 0;
    sh[tid] = v;
    __syncthreads();
    for (int off = 1; off < 128; off <<= 1) {
        int t = (tid >= off) ? sh[tid - off] : 0;
        __syncthreads();
        sh[tid] += t;
        __syncthreads();
    }
    if (tid < SCAN_NB) g_bpref[tid] = sh[tid] - v;   // exclusive
}

__global__ void k_scan() {       // SCAN_NB blocks, 1024 threads
    __shared__ int sh[1024];
    int tid = threadIdx.x;
    int i = blockIdx.x * 1024 + tid;
    int v = (i < N_NODES) ? g_deg[i] : 0;
    sh[tid] = v;
    __syncthreads();
    for (int off = 1; off < 1024; off <<= 1) {
        int t = (tid >= off) ? sh[tid - off] : 0;
        __syncthreads();
        sh[tid] += t;
        __syncthreads();
    }
    int excl = g_bpref[blockIdx.x] + sh[tid] - v;
    if (i < N_NODES) {
        g_off[i]  = excl;
        g_fill[i] = excl;
        if (i == N_NODES - 1) g_off[N_NODES] = excl + v;
    }
}

__global__ void k_fill(const int* __restrict__ src, const int* __restrict__ dst) {
    int e = blockIdx.x * blockDim.x + threadIdx.x;
    if (e < N_EDGES) {
        int slot = atomicAdd(&g_fill[dst[e]], 1);
        g_csrc[slot] = src[e];
    }
}

// ---------------- fused: mean-aggregate + relu(x@Wa+ba) + softmax(@Wb+bb) + pool ----
// Warp per node. Gather layout: lane holds features (2*lane, 2*lane+1) as float2.
// Layer-1/2 outputs use layout (lane, lane+32).
// pass 0: x = feat, writes g_f, pools into g_fg
// pass 1: x = g_f, pools into g_hg
__global__ void __launch_bounds__(256) k_gcn(
    const float* __restrict__ x_feat,
    const float* __restrict__ Wa, const float* __restrict__ ba,
    const float* __restrict__ Wb, const float* __restrict__ bb,
    const int* __restrict__ gid, int pass)
{
    __shared__ float2 sWa[64 * 32];     // sWa[k*32+j] = (Wa[k][j], Wa[k][j+32])
    __shared__ float2 sWb[64 * 32];
    __shared__ float  sba[64], sbb[64];
    __shared__ float  spool[64];
    __shared__ int    sgid[8];

    const float* __restrict__ x    = pass ? g_f : x_feat;
    float*       __restrict__ pool = pass ? g_hg : g_fg;

    int tid = threadIdx.x;
    for (int idx = tid; idx < 64 * 32; idx += 256) {
        int k = idx >> 5, j = idx & 31;
        sWa[idx] = make_float2(Wa[k * 64 + j], Wa[k * 64 + j + 32]);
        sWb[idx] = make_float2(Wb[k * 64 + j], Wb[k * 64 + j + 32]);
    }
    if (tid < 64) { sba[tid] = ba[tid]; sbb[tid] = bb[tid]; }

    int warp = tid >> 5, lane = tid & 31;
    const int NTILES = N_NODES / 8;     // 12500

    for (int tile = blockIdx.x; tile < NTILES; tile += gridDim.x) {
        int row = tile * 8 + warp;

        __syncthreads();                       // spool/sgid reuse + (iter0) weight staging
        if (tid < 64) spool[tid] = 0.f;
        if (lane == 0) sgid[warp] = gid[row];
        __syncthreads();

        // ---- mean aggregation ----
        int s0 = g_off[row], s1 = g_off[row + 1];
        float2 acc = make_float2(0.f, 0.f);
        for (int e = s0; e < s1; e++) {
            int s = g_csrc[e];
            float2 v = *(const float2*)(x + (size_t)s * D + lane * 2);
            acc.x += v.x; acc.y += v.y;
        }
        float2 xv;
        if (s1 > s0) {
            float inv = 1.f / (float)(s1 - s0);
            xv = make_float2(acc.x * inv, acc.y * inv);
        } else {
            xv = *(const float2*)(x + (size_t)row * D + lane * 2);
        }

        // ---- layer 1: relu(x@Wa+ba) -> outputs (lane, lane+32) ----
        float a0 = sba[lane], a1 = sba[lane + 32];
        #pragma unroll
        for (int kk = 0; kk < 32; kk++) {
            float xa = __shfl_sync(0xffffffffu, xv.x, kk);  // feature 2*kk
            float xb = __shfl_sync(0xffffffffu, xv.y, kk);  // feature 2*kk+1
            float2 w0 = sWa[(2 * kk)     * 32 + lane];
            float2 w1 = sWa[(2 * kk + 1) * 32 + lane];
            a0 = fmaf(xa, w0.x, a0); a1 = fmaf(xa, w0.y, a1);
            a0 = fmaf(xb, w1.x, a0); a1 = fmaf(xb, w1.y, a1);
        }
        float h0 = fmaxf(a0, 0.f), h1 = fmaxf(a1, 0.f);

        // ---- layer 2: h@Wb+bb ----
        float z0 = sbb[lane], z1 = sbb[lane + 32];
        #pragma unroll
        for (int k = 0; k < 32; k++) {
            float hk = __shfl_sync(0xffffffffu, h0, k);
            float2 w = sWb[k * 32 + lane];
            z0 = fmaf(hk, w.x, z0); z1 = fmaf(hk, w.y, z1);
        }
        #pragma unroll
        for (int k = 0; k < 32; k++) {
            float hk = __shfl_sync(0xffffffffu, h1, k);
            float2 w = sWb[(k + 32) * 32 + lane];
            z0 = fmaf(hk, w.x, z0); z1 = fmaf(hk, w.y, z1);
        }

        // ---- softmax over 64 features ----
        float m = fmaxf(z0, z1);
        #pragma unroll
        for (int o = 16; o > 0; o >>= 1) m = fmaxf(m, __shfl_xor_sync(0xffffffffu, m, o));
        float e0 = __expf(z0 - m), e1 = __expf(z1 - m);
        float s = e0 + e1;
        #pragma unroll
        for (int o = 16; o > 0; o >>= 1) s += __shfl_xor_sync(0xffffffffu, s, o);
        float rinv = 1.f / s;
        float r0 = e0 * rinv, r1 = e1 * rinv;

        if (pass == 0) {
            float* o_ = g_f + (size_t)row * D;
            o_[lane] = r0; o_[lane + 32] = r1;
        }

        // ---- graph pooling (graph_ids sorted -> tile usually single-graph) ----
        bool same = (sgid[0] == sgid[1]) && (sgid[1] == sgid[2]) && (sgid[2] == sgid[3]) &&
                    (sgid[3] == sgid[4]) && (sgid[4] == sgid[5]) && (sgid[5] == sgid[6]) &&
                    (sgid[6] == sgid[7]);
        if (same) {
            atomicAdd(&spool[lane],      r0);
            atomicAdd(&spool[lane + 32], r1);
            __syncthreads();
            if (tid < 64) atomicAdd(&pool[sgid[0] * D + tid], spool[tid]);
        } else {
            int g = sgid[warp];
            atomicAdd(&pool[g * D + lane],      r0);
            atomicAdd(&pool[g * D + lane + 32], r1);
        }
    }
}

// ---------------- classifier head: warp per graph ----------------
__global__ void __launch_bounds__(1024) k_final(
    const float* __restrict__ Wd, const float* __restrict__ bd,
    const float* __restrict__ Wc, const float* __restrict__ bc,
    float* __restrict__ out)
{
    __shared__ float2 sWd[128 * 32];
    __shared__ float  sbd[64], sWc[64];
    int tid = threadIdx.x;
    for (int idx = tid; idx < 128 * 32; idx += 1024) {
        int k = idx >> 5, j = idx & 31;
        sWd[idx] = make_float2(Wd[k * 64 + j], Wd[k * 64 + j + 32]);
    }
    if (tid < 64) { sbd[tid] = bd[tid]; sWc[tid] = Wc[tid]; }
    __syncthreads();

    int warp = tid >> 5, lane = tid & 31;
    int g = blockIdx.x * 32 + warp;
    if (g >= N_GRAPHS) return;

    float xc0 = g_fg[g * D + lane];
    float xc1 = g_fg[g * D + lane + 32];
    float xc2 = xc0 + g_hg[g * D + lane];
    float xc3 = xc1 + g_hg[g * D + lane + 32];

    float a0 = sbd[lane], a1 = sbd[lane + 32];
    #pragma unroll
    for (int k = 0; k < 32; k++) {
        float xk = __shfl_sync(0xffffffffu, xc0, k);
        float2 w = sWd[k * 32 + lane];
        a0 = fmaf(xk, w.x, a0); a1 = fmaf(xk, w.y, a1);
    }
    #pragma unroll
    for (int k = 0; k < 32; k++) {
        float xk = __shfl_sync(0xffffffffu, xc1, k);
        float2 w = sWd[(k + 32) * 32 + lane];
        a0 = fmaf(xk, w.x, a0); a1 = fmaf(xk, w.y, a1);
    }
    #pragma unroll
    for (int k = 0; k < 32; k++) {
        float xk = __shfl_sync(0xffffffffu, xc2, k);
        float2 w = sWd[(k + 64) * 32 + lane];
        a0 = fmaf(xk, w.x, a0); a1 = fmaf(xk, w.y, a1);
    }
    #pragma unroll
    for (int k = 0; k < 32; k++) {
        float xk = __shfl_sync(0xffffffffu, xc3, k);
        float2 w = sWd[(k + 96) * 32 + lane];
        a0 = fmaf(xk, w.x, a0); a1 = fmaf(xk, w.y, a1);
    }
    float r0 = fmaxf(a0, 0.f), r1 = fmaxf(a1, 0.f);
    float p = r0 * sWc[lane] + r1 * sWc[lane + 32];
    #pragma unroll
    for (int o = 16; o > 0; o >>= 1) p += __shfl_xor_sync(0xffffffffu, p, o);
    if (lane == 0) out[g] = p + bc[0];
}

// ---------------- launch ----------------
extern "C" void kernel_launch(void* const* d_in, const int* in_sizes, int n_in,
                              void* d_out, int out_size)
{
    const float* feat = (const float*)d_in[0];
    const int*   src  = (const int*)  d_in[1];
    const int*   dst  = (const int*)  d_in[2];
    const int*   gid  = (const int*)  d_in[3];
    const float* W1   = (const float*)d_in[4];
    const float* b1   = (const float*)d_in[5];
    const float* Ws1  = (const float*)d_in[6];
    const float* bs1  = (const float*)d_in[7];
    const float* W2   = (const float*)d_in[8];
    const float* b2   = (const float*)d_in[9];
    const float* Ws2  = (const float*)d_in[10];
    const float* bs2  = (const float*)d_in[11];
    const float* Wd   = (const float*)d_in[12];
    const float* bd   = (const float*)d_in[13];
    const float* Wc   = (const float*)d_in[14];
    const float* bc   = (const float*)d_in[15];
    float* out = (float*)d_out;

    k_zero   <<<(N_NODES + 255) / 256, 256>>>();
    k_hist   <<<N_EDGES / 256, 256>>>(dst);
    k_breduce<<<SCAN_NB, 1024>>>();
    k_bscan  <<<1, 128>>>();
    k_scan   <<<SCAN_NB, 1024>>>();
    k_fill   <<<N_EDGES / 256, 256>>>(src, dst);

    k_gcn  <<<GCN_GRID, 256>>>(feat, W1, b1, Ws1, bs1, gid, 0);  // agg(feat)+MLP1 -> g_f, g_fg
    k_gcn  <<<GCN_GRID, 256>>>(feat, W2, b2, Ws2, bs2, gid, 1);  // agg(g_f)+MLP2  -> g_hg
    k_final<<<4, 1024>>>(Wd, bd, Wc, bc, out);
}